// round 1
// baseline (speedup 1.0000x reference)
#include <cuda_runtime.h>

// -----------------------------------------------------------------------------
// VariableLengthFlashSelfAttentionWithT5Mask — Round 0 baseline (fp32 SIMT flash)
//
// Two stages, interleaved batch. Per (sample, head): dense seqlen x seqlen
// non-causal attention where the first 128 tokens come from the encoder
// tensors and the rest from the stage's slice of the video tensors.
// Output is packed: stage0 samples' valid rows, then stage1's.
//
// Tiling: BQ=32 query rows x BK=64 key rows per iteration, D=64.
// 128 threads; thread (qg=tid>>4, kg=tid&15) owns a 4x4 micro-tile:
//   rows {qg+8i}, key-cols / d-cols {kg+16j}. All data strided so each
//   8-lane LDS.128 phase hits distinct 16B super-banks (K/Vt rows padded to 68).
// Online softmax: row stats reduced over the 16 lanes that share qg via
// __shfl_xor; P tile is produced and consumed by the same 16 lanes, so only
// __syncwarp() is needed around it (no block barrier in the softmax path).
// -----------------------------------------------------------------------------

#define H  16
#define D  64
#define BQ 32
#define BK 64
#define NT 128

// unit u = 0..3 -> stage 0 samples, 4..7 -> stage 1 samples
__constant__ int c_seqlen[8] = {640, 480, 560, 400, 1152, 864, 1008, 720};
__constant__ int c_qstart[8] = {0, 20, 35, 53, 66, 102, 129, 161};   // cum ceil(seq/32); total 184
__constant__ int c_obase[8]  = {0, 640, 1120, 1680, 2080, 3232, 4096, 5104};
__constant__ int c_batch[8]  = {0, 2, 4, 6, 1, 3, 5, 7};
__constant__ int c_soff[8]   = {0, 0, 0, 0, 512, 512, 512, 512};

#define KS_STRIDE 68                  // floats per K/Vt row (272B = 17 x 16B -> float4-aligned, conflict-free)
#define SM_QS 0                       // Qs: 32 x 64 floats (pre-scaled by 0.125)
#define SM_KS (32*64)                 // Ks: 64 x 68
#define SM_VT (SM_KS + 64*KS_STRIDE) // Vt: 64 x 68 (transposed: [d][k])
#define SM_PS (SM_VT + 64*KS_STRIDE) // Ps: 32 x 64
#define SM_TOTAL_FLOATS (SM_PS + 32*64)

__global__ __launch_bounds__(NT) void fa_fp32_kernel(
    const float* __restrict__ gq, const float* __restrict__ gk, const float* __restrict__ gv,
    const float* __restrict__ eq, const float* __restrict__ ek, const float* __restrict__ ev,
    float* __restrict__ gout)
{
    extern __shared__ float smem[];
    float* Qs = smem + SM_QS;
    float* Ks = smem + SM_KS;
    float* Vt = smem + SM_VT;
    float* Ps = smem + SM_PS;

    const int h  = blockIdx.y;
    const int bx = blockIdx.x;
    int u = 0;
    #pragma unroll
    for (int i = 1; i < 8; i++) u += (bx >= c_qstart[i]);
    const int seqlen = c_seqlen[u];
    const int q0     = (bx - c_qstart[u]) * BQ;
    const int b      = c_batch[u];
    const int soff   = c_soff[u];
    const int obase  = c_obase[u];

    const int tid = threadIdx.x;
    const int qg  = tid >> 4;   // 0..7  : query row group (rows qg+8i)
    const int kg  = tid & 15;   // 0..15 : key-col / d-col group (cols kg+16j)

    // ---- Load Q tile (pre-scaled by softmax scale 1/sqrt(64)=0.125) ----
    #pragma unroll
    for (int it = 0; it < 4; it++) {
        int idx = tid + NT * it;            // 0..511 = 32 rows x 16 float4
        int row = idx >> 4, c4 = idx & 15;
        int rg  = q0 + row;                 // < ceil32(seqlen) <= lc, always valid memory
        const float* src = (rg < 128)
            ? (eq + (((b * 128  + rg            ) * H + h) * D) + 4 * c4)
            : (gq + (((b * 1536 + soff + rg - 128) * H + h) * D) + 4 * c4);
        float4 val = *(const float4*)src;
        val.x *= 0.125f; val.y *= 0.125f; val.z *= 0.125f; val.w *= 0.125f;
        *(float4*)(Qs + row * 64 + 4 * c4) = val;
    }

    float m_i[4], l_i[4], o[4][4];
    #pragma unroll
    for (int i = 0; i < 4; i++) {
        m_i[i] = -1e30f; l_i[i] = 0.f;
        #pragma unroll
        for (int j = 0; j < 4; j++) o[i][j] = 0.f;
    }

    const int ktiles = (seqlen + BK - 1) / BK;   // fully-masked tiles skipped entirely
    for (int kt = 0; kt < ktiles; kt++) {
        const int k0 = kt * BK;
        __syncthreads();   // previous tile's Ks/Vt consumers done

        // ---- Load K tile (64 rows x 16 float4) ----
        #pragma unroll
        for (int it = 0; it < 8; it++) {
            int idx = tid + NT * it;
            int row = idx >> 4, c4 = idx & 15;
            int rg  = k0 + row;                 // < ceil64(seqlen) <= lc, valid memory
            const float* src = (rg < 128)
                ? (ek + (((b * 128  + rg            ) * H + h) * D) + 4 * c4)
                : (gk + (((b * 1536 + soff + rg - 128) * H + h) * D) + 4 * c4);
            *(float4*)(Ks + row * KS_STRIDE + 4 * c4) = *(const float4*)src;
        }
        // ---- Load V tile transposed into Vt[d][k] ----
        #pragma unroll
        for (int it = 0; it < 8; it++) {
            int idx = tid + NT * it;
            int row = idx >> 4, c4 = idx & 15;
            int rg  = k0 + row;
            const float* src = (rg < 128)
                ? (ev + (((b * 128  + rg            ) * H + h) * D) + 4 * c4)
                : (gv + (((b * 1536 + soff + rg - 128) * H + h) * D) + 4 * c4);
            float4 val = *(const float4*)src;
            Vt[(4 * c4 + 0) * KS_STRIDE + row] = val.x;
            Vt[(4 * c4 + 1) * KS_STRIDE + row] = val.y;
            Vt[(4 * c4 + 2) * KS_STRIDE + row] = val.z;
            Vt[(4 * c4 + 3) * KS_STRIDE + row] = val.w;
        }
        __syncthreads();

        // ---- S = Q K^T (4x4 micro-tile in registers) ----
        float acc[4][4];
        #pragma unroll
        for (int i = 0; i < 4; i++)
            #pragma unroll
            for (int j = 0; j < 4; j++) acc[i][j] = 0.f;

        #pragma unroll
        for (int d4 = 0; d4 < 16; d4++) {
            float4 qv[4], kv[4];
            #pragma unroll
            for (int i = 0; i < 4; i++)
                qv[i] = *(const float4*)(Qs + (qg + 8 * i) * 64 + 4 * d4);
            #pragma unroll
            for (int j = 0; j < 4; j++)
                kv[j] = *(const float4*)(Ks + (kg + 16 * j) * KS_STRIDE + 4 * d4);
            #pragma unroll
            for (int i = 0; i < 4; i++)
                #pragma unroll
                for (int j = 0; j < 4; j++)
                    acc[i][j] += qv[i].x * kv[j].x + qv[i].y * kv[j].y
                               + qv[i].z * kv[j].z + qv[i].w * kv[j].w;
        }

        // ---- key-validity mask (per column) ----
        #pragma unroll
        for (int j = 0; j < 4; j++) {
            if (k0 + kg + 16 * j >= seqlen) {
                #pragma unroll
                for (int i = 0; i < 4; i++) acc[i][j] = -1e30f;
            }
        }

        // ---- online softmax (row stats across the 16 lanes sharing qg) ----
        #pragma unroll
        for (int i = 0; i < 4; i++) {
            float tm = acc[i][0];
            #pragma unroll
            for (int j = 1; j < 4; j++) tm = fmaxf(tm, acc[i][j]);
            #pragma unroll
            for (int off = 1; off < 16; off <<= 1)
                tm = fmaxf(tm, __shfl_xor_sync(0xffffffffu, tm, off));
            const float nm    = fmaxf(m_i[i], tm);
            const float alpha = __expf(m_i[i] - nm);
            m_i[i] = nm;
            float ts = 0.f;
            #pragma unroll
            for (int j = 0; j < 4; j++) {
                float p = __expf(acc[i][j] - nm);   // masked -> exact 0 (underflow)
                acc[i][j] = p;
                ts += p;
            }
            #pragma unroll
            for (int off = 1; off < 16; off <<= 1)
                ts += __shfl_xor_sync(0xffffffffu, ts, off);
            l_i[i] = l_i[i] * alpha + ts;
            #pragma unroll
            for (int j = 0; j < 4; j++) o[i][j] *= alpha;
            // stage P through smem (same 16 lanes produce & consume these rows)
            #pragma unroll
            for (int j = 0; j < 4; j++)
                Ps[(qg + 8 * i) * 64 + kg + 16 * j] = acc[i][j];
        }
        __syncwarp();

        // ---- O += P V (4x4 micro-tile, kg reused as d-col group) ----
        #pragma unroll
        for (int k4 = 0; k4 < 16; k4++) {
            float4 pv[4], vv[4];
            #pragma unroll
            for (int i = 0; i < 4; i++)
                pv[i] = *(const float4*)(Ps + (qg + 8 * i) * 64 + 4 * k4);
            #pragma unroll
            for (int j = 0; j < 4; j++)
                vv[j] = *(const float4*)(Vt + (kg + 16 * j) * KS_STRIDE + 4 * k4);
            #pragma unroll
            for (int i = 0; i < 4; i++)
                #pragma unroll
                for (int j = 0; j < 4; j++)
                    o[i][j] += pv[i].x * vv[j].x + pv[i].y * vv[j].y
                             + pv[i].z * vv[j].z + pv[i].w * vv[j].w;
        }
        __syncwarp();   // Ps consumed before next tile overwrites it
    }

    // ---- epilogue: normalize + packed scatter ----
    #pragma unroll
    for (int i = 0; i < 4; i++) {
        const int qrow = q0 + qg + 8 * i;
        if (qrow < seqlen) {
            const float inv = 1.f / l_i[i];
            #pragma unroll
            for (int j = 0; j < 4; j++)
                gout[(((long)(obase + qrow)) * H + h) * D + kg + 16 * j] = o[i][j] * inv;
        }
    }
}

extern "C" void kernel_launch(void* const* d_in, const int* in_sizes, int n_in,
                              void* d_out, int out_size)
{
    const float* gq = (const float*)d_in[0];
    const float* gk = (const float*)d_in[1];
    const float* gv = (const float*)d_in[2];
    const float* eq = (const float*)d_in[3];
    const float* ek = (const float*)d_in[4];
    const float* ev = (const float*)d_in[5];
    float* out = (float*)d_out;

    const size_t smem_bytes = SM_TOTAL_FLOATS * sizeof(float);   // 51200 B
    cudaFuncSetAttribute(fa_fp32_kernel,
                         cudaFuncAttributeMaxDynamicSharedMemorySize,
                         (int)smem_bytes);

    dim3 grid(184, H, 1);   // 184 q-tiles across the 8 (stage,sample) units x 16 heads
    fa_fp32_kernel<<<grid, NT, smem_bytes>>>(gq, gk, gv, eq, ek, ev, out);
}

// round 2
// speedup vs baseline: 3.8024x; 3.8024x over previous
#include <cuda_runtime.h>

// -----------------------------------------------------------------------------
// Round 2: tf32 mma.sync flash attention.
// BQ=64 x BK=64, D=64, 128 threads (4 warps, 16 q-rows each).
// S and O live in m16n8 accumulator fragments; P staged through smem (warp-
// private rows). K/V double-buffered via cp.async. Q pre-scaled by 0.125*log2e
// so softmax uses ex2.approx directly.
// -----------------------------------------------------------------------------

#define NT 128
#define QKSCALE (0.125f * 1.44269504088896f)

// units sorted by descending seqlen for tail packing
__constant__ int c_seqlen[8] = {1152, 1008, 864, 720, 640, 560, 480, 400};
__constant__ int c_batch[8]  = {1,    5,    3,   7,   0,   4,   2,   6};
__constant__ int c_soff[8]   = {512,  512,  512, 512, 0,   0,   0,   0};
__constant__ int c_obase[8]  = {2080, 4096, 3232, 5104, 0, 1120, 640, 1680};
__constant__ int c_qstart[8] = {0, 18, 34, 48, 60, 70, 79, 87};   // cum ceil(seq/64); total 94

#define QS_STRIDE 68
#define KS_STRIDE 68
#define VS_STRIDE 72
#define PS_STRIDE 68
// smem float offsets
#define SM_QS  0
#define SM_KS0 (SM_QS + 64*QS_STRIDE)            // 4352
#define SM_KS1 (SM_KS0 + 64*KS_STRIDE)           // 8704
#define SM_VS0 (SM_KS1 + 64*KS_STRIDE)           // 13056
#define SM_VS1 (SM_VS0 + 64*VS_STRIDE)           // 17664
#define SM_PS  (SM_VS1 + 64*VS_STRIDE)           // 22272
#define SM_TOTAL_FLOATS (SM_PS + 64*PS_STRIDE)   // 26624 floats = 106496 B

__device__ __forceinline__ unsigned f2tf(float f) {
    unsigned u; asm("cvt.rna.tf32.f32 %0, %1;" : "=r"(u) : "f"(f)); return u;
}
__device__ __forceinline__ float ex2(float x) {
    float y; asm("ex2.approx.f32 %0, %1;" : "=f"(y) : "f"(x)); return y;
}
__device__ __forceinline__ void mma8(float d[4], const unsigned a[4], unsigned b0, unsigned b1) {
    asm volatile("mma.sync.aligned.m16n8k8.row.col.f32.tf32.tf32.f32 "
                 "{%0,%1,%2,%3}, {%4,%5,%6,%7}, {%8,%9}, {%0,%1,%2,%3};"
                 : "+f"(d[0]), "+f"(d[1]), "+f"(d[2]), "+f"(d[3])
                 : "r"(a[0]), "r"(a[1]), "r"(a[2]), "r"(a[3]), "r"(b0), "r"(b1));
}
__device__ __forceinline__ void cpa16(float* s, const float* g) {
    unsigned sa = (unsigned)__cvta_generic_to_shared(s);
    asm volatile("cp.async.cg.shared.global [%0], [%1], 16;" :: "r"(sa), "l"(g));
}
#define CP_COMMIT() asm volatile("cp.async.commit_group;")
template <int N> __device__ __forceinline__ void cp_wait() {
    asm volatile("cp.async.wait_group %0;" :: "n"(N));
}

__global__ __launch_bounds__(NT) void fa_tf32_kernel(
    const float* __restrict__ gq, const float* __restrict__ gk, const float* __restrict__ gv,
    const float* __restrict__ eq, const float* __restrict__ ek, const float* __restrict__ ev,
    float* __restrict__ gout)
{
    extern __shared__ float sm[];
    float* Qs = sm + SM_QS;
    float* Ksb[2] = { sm + SM_KS0, sm + SM_KS1 };
    float* Vsb[2] = { sm + SM_VS0, sm + SM_VS1 };
    float* Ps = sm + SM_PS;

    const int h  = blockIdx.y;
    const int bx = blockIdx.x;
    int u = 0;
    #pragma unroll
    for (int i = 1; i < 8; i++) u += (bx >= c_qstart[i]);
    const int seqlen = c_seqlen[u];
    const int q0     = (bx - c_qstart[u]) * 64;
    const int b      = c_batch[u];
    const int soff   = c_soff[u];
    const int obase  = c_obase[u];

    const int tid  = threadIdx.x;
    const int wid  = tid >> 5;
    const int lane = tid & 31;
    const int gID  = lane >> 2;   // 0..7  row-in-fragment group
    const int t4   = lane & 3;    // 0..3
    const int m0   = wid * 16;    // warp's local q-row base

    // ---- Q load: scale by 0.125*log2e, cvt to tf32, store to smem ----
    #pragma unroll
    for (int it = 0; it < 8; it++) {
        int idx = tid + NT * it;           // 0..1023 = 64 rows x 16 float4
        int row = idx >> 4, c4 = idx & 15;
        int rg  = q0 + row;                // < ceil64(seqlen) <= lc: valid memory
        const float* src = (rg < 128)
            ? (eq + (((b * 128  + rg            ) * 16 + h) * 64) + 4 * c4)
            : (gq + (((b * 1536 + soff + rg - 128) * 16 + h) * 64) + 4 * c4);
        float4 v = *(const float4*)src;
        uint4 o;
        o.x = f2tf(v.x * QKSCALE); o.y = f2tf(v.y * QKSCALE);
        o.z = f2tf(v.z * QKSCALE); o.w = f2tf(v.w * QKSCALE);
        *(uint4*)(Qs + row * QS_STRIDE + 4 * c4) = o;
    }

    const int ktiles = (seqlen + 63) >> 6;

    // ---- issue tile 0 K/V loads (cp.async, raw fp32 -> HW tf32 truncation) ----
    #pragma unroll
    for (int it = 0; it < 8; it++) {
        int idx = tid + NT * it;
        int row = idx >> 4, c4 = idx & 15;
        int rg  = row;   // k0 = 0
        const float* sk = (rg < 128)
            ? (ek + (((b * 128  + rg            ) * 16 + h) * 64) + 4 * c4)
            : (gk + (((b * 1536 + soff + rg - 128) * 16 + h) * 64) + 4 * c4);
        const float* sv = (rg < 128)
            ? (ev + (((b * 128  + rg            ) * 16 + h) * 64) + 4 * c4)
            : (gv + (((b * 1536 + soff + rg - 128) * 16 + h) * 64) + 4 * c4);
        cpa16(Ksb[0] + row * KS_STRIDE + 4 * c4, sk);
        cpa16(Vsb[0] + row * VS_STRIDE + 4 * c4, sv);
    }
    CP_COMMIT();

    __syncthreads();   // Qs visible to all warps

    // ---- Q fragments (persistent): qf[kc][0..3] for k-chunks of 8 ----
    unsigned qf[8][4];
    #pragma unroll
    for (int kc = 0; kc < 8; kc++) {
        qf[kc][0] = __float_as_uint(Qs[(m0 + gID    ) * QS_STRIDE + kc * 8 + t4    ]);
        qf[kc][1] = __float_as_uint(Qs[(m0 + gID + 8) * QS_STRIDE + kc * 8 + t4    ]);
        qf[kc][2] = __float_as_uint(Qs[(m0 + gID    ) * QS_STRIDE + kc * 8 + t4 + 4]);
        qf[kc][3] = __float_as_uint(Qs[(m0 + gID + 8) * QS_STRIDE + kc * 8 + t4 + 4]);
    }

    float mA = -1e30f, mB = -1e30f, lA = 0.f, lB = 0.f;
    float oacc[8][4];
    #pragma unroll
    for (int nc = 0; nc < 8; nc++)
        #pragma unroll
        for (int j = 0; j < 4; j++) oacc[nc][j] = 0.f;

    for (int kt = 0; kt < ktiles; kt++) {
        float* Kc = Ksb[kt & 1];
        float* Vc = Vsb[kt & 1];

        // issue next tile into the other buffer (its old contents were last
        // read in iter kt-1; end-of-iter barrier protects the overwrite)
        if (kt + 1 < ktiles) {
            const int k0n = (kt + 1) * 64;
            float* Kn = Ksb[(kt + 1) & 1];
            float* Vn = Vsb[(kt + 1) & 1];
            #pragma unroll
            for (int it = 0; it < 8; it++) {
                int idx = tid + NT * it;
                int row = idx >> 4, c4 = idx & 15;
                int rg  = k0n + row;
                const float* sk = (rg < 128)
                    ? (ek + (((b * 128  + rg            ) * 16 + h) * 64) + 4 * c4)
                    : (gk + (((b * 1536 + soff + rg - 128) * 16 + h) * 64) + 4 * c4);
                const float* sv = (rg < 128)
                    ? (ev + (((b * 128  + rg            ) * 16 + h) * 64) + 4 * c4)
                    : (gv + (((b * 1536 + soff + rg - 128) * 16 + h) * 64) + 4 * c4);
                cpa16(Kn + row * KS_STRIDE + 4 * c4, sk);
                cpa16(Vn + row * VS_STRIDE + 4 * c4, sv);
            }
            CP_COMMIT();
            cp_wait<1>();   // current tile's group complete; next may fly
        } else {
            cp_wait<0>();
        }
        __syncthreads();

        // ---- S = Q K^T : 8 n-chunks x 8 k-chunks of m16n8k8 ----
        float sacc[8][4];
        #pragma unroll
        for (int nc = 0; nc < 8; nc++) {
            sacc[nc][0] = 0.f; sacc[nc][1] = 0.f; sacc[nc][2] = 0.f; sacc[nc][3] = 0.f;
            #pragma unroll
            for (int kc = 0; kc < 8; kc++) {
                unsigned b0 = __float_as_uint(Kc[(nc * 8 + gID) * KS_STRIDE + kc * 8 + t4    ]);
                unsigned b1 = __float_as_uint(Kc[(nc * 8 + gID) * KS_STRIDE + kc * 8 + t4 + 4]);
                mma8(sacc[nc], qf[kc], b0, b1);
            }
        }

        // ---- key-validity mask ----
        const int kbase = kt * 64;
        #pragma unroll
        for (int nc = 0; nc < 8; nc++) {
            int col0 = kbase + nc * 8 + 2 * t4;
            if (col0     >= seqlen) { sacc[nc][0] = -1e30f; sacc[nc][2] = -1e30f; }
            if (col0 + 1 >= seqlen) { sacc[nc][1] = -1e30f; sacc[nc][3] = -1e30f; }
        }

        // ---- online softmax (rows rA = gID, rB = gID+8; stats over 4 lanes) ----
        float rmA = -1e30f, rmB = -1e30f;
        #pragma unroll
        for (int nc = 0; nc < 8; nc++) {
            rmA = fmaxf(rmA, fmaxf(sacc[nc][0], sacc[nc][1]));
            rmB = fmaxf(rmB, fmaxf(sacc[nc][2], sacc[nc][3]));
        }
        rmA = fmaxf(rmA, __shfl_xor_sync(0xffffffffu, rmA, 1));
        rmA = fmaxf(rmA, __shfl_xor_sync(0xffffffffu, rmA, 2));
        rmB = fmaxf(rmB, __shfl_xor_sync(0xffffffffu, rmB, 1));
        rmB = fmaxf(rmB, __shfl_xor_sync(0xffffffffu, rmB, 2));

        const float nmA = fmaxf(mA, rmA), nmB = fmaxf(mB, rmB);
        const float aA = ex2(mA - nmA), aB = ex2(mB - nmB);
        mA = nmA; mB = nmB;

        float sumA = 0.f, sumB = 0.f;
        #pragma unroll
        for (int nc = 0; nc < 8; nc++) {
            float p0 = ex2(sacc[nc][0] - nmA);
            float p1 = ex2(sacc[nc][1] - nmA);
            float p2 = ex2(sacc[nc][2] - nmB);
            float p3 = ex2(sacc[nc][3] - nmB);
            sumA += p0 + p1; sumB += p2 + p3;
            uint2 wA; wA.x = f2tf(p0); wA.y = f2tf(p1);
            uint2 wB; wB.x = f2tf(p2); wB.y = f2tf(p3);
            *(uint2*)(Ps + (m0 + gID    ) * PS_STRIDE + nc * 8 + 2 * t4) = wA;
            *(uint2*)(Ps + (m0 + gID + 8) * PS_STRIDE + nc * 8 + 2 * t4) = wB;
        }
        sumA += __shfl_xor_sync(0xffffffffu, sumA, 1);
        sumA += __shfl_xor_sync(0xffffffffu, sumA, 2);
        sumB += __shfl_xor_sync(0xffffffffu, sumB, 1);
        sumB += __shfl_xor_sync(0xffffffffu, sumB, 2);
        lA = lA * aA + sumA;
        lB = lB * aB + sumB;

        #pragma unroll
        for (int nc = 0; nc < 8; nc++) {
            oacc[nc][0] *= aA; oacc[nc][1] *= aA;
            oacc[nc][2] *= aB; oacc[nc][3] *= aB;
        }
        __syncwarp();   // warp-private Ps rows written before reads

        // ---- O += P V : k over keys (8 chunks), n over d (8 chunks) ----
        #pragma unroll
        for (int kc = 0; kc < 8; kc++) {
            unsigned a[4];
            a[0] = __float_as_uint(Ps[(m0 + gID    ) * PS_STRIDE + kc * 8 + t4    ]);
            a[1] = __float_as_uint(Ps[(m0 + gID + 8) * PS_STRIDE + kc * 8 + t4    ]);
            a[2] = __float_as_uint(Ps[(m0 + gID    ) * PS_STRIDE + kc * 8 + t4 + 4]);
            a[3] = __float_as_uint(Ps[(m0 + gID + 8) * PS_STRIDE + kc * 8 + t4 + 4]);
            #pragma unroll
            for (int nc = 0; nc < 8; nc++) {
                unsigned b0 = __float_as_uint(Vc[(kc * 8 + t4    ) * VS_STRIDE + nc * 8 + gID]);
                unsigned b1 = __float_as_uint(Vc[(kc * 8 + t4 + 4) * VS_STRIDE + nc * 8 + gID]);
                mma8(oacc[nc], a, b0, b1);
            }
        }
        __syncthreads();   // all warps done with Kc/Vc (and Ps) before overwrite
    }

    // ---- epilogue: normalize + packed store ----
    const float invA = 1.f / lA, invB = 1.f / lB;
    const int qrA = q0 + m0 + gID;
    const int qrB = qrA + 8;
    #pragma unroll
    for (int nc = 0; nc < 8; nc++) {
        const int col = nc * 8 + 2 * t4;
        if (qrA < seqlen) {
            float2 v; v.x = oacc[nc][0] * invA; v.y = oacc[nc][1] * invA;
            *(float2*)(gout + (((long)(obase + qrA)) * 16 + h) * 64 + col) = v;
        }
        if (qrB < seqlen) {
            float2 v; v.x = oacc[nc][2] * invB; v.y = oacc[nc][3] * invB;
            *(float2*)(gout + (((long)(obase + qrB)) * 16 + h) * 64 + col) = v;
        }
    }
}

extern "C" void kernel_launch(void* const* d_in, const int* in_sizes, int n_in,
                              void* d_out, int out_size)
{
    const float* gq = (const float*)d_in[0];
    const float* gk = (const float*)d_in[1];
    const float* gv = (const float*)d_in[2];
    const float* eq = (const float*)d_in[3];
    const float* ek = (const float*)d_in[4];
    const float* ev = (const float*)d_in[5];
    float* out = (float*)d_out;

    const size_t smem_bytes = SM_TOTAL_FLOATS * sizeof(float);   // 106496 B
    cudaFuncSetAttribute(fa_tf32_kernel,
                         cudaFuncAttributeMaxDynamicSharedMemorySize,
                         (int)smem_bytes);

    dim3 grid(94, 16, 1);   // 94 q-tiles (BQ=64) x 16 heads
    fa_tf32_kernel<<<grid, NT, smem_bytes>>>(gq, gk, gv, eq, ek, ev, out);
}